// round 4
// baseline (speedup 1.0000x reference)
#include <cuda_runtime.h>

// Problem constants
#define Bb   8
#define Cc   256
#define Nn   2048
#define Kk   16
#define OUTd 256
#define KD   512                 // 2*C
#define BN_TOT (Bb*Nn)           // 16384

// ---- scratch (static device globals; no dynamic allocation) ----
__device__ float g_xsT [BN_TOT * Cc];   // [B*N, C] node-major features
__device__ float g_si  [BN_TOT];
__device__ float g_sj  [BN_TOT];
__device__ float g_w   [BN_TOT * Kk];   // softmax weights
__device__ int   g_j   [BN_TOT * Kk];   // neighbor indices (int32)
__device__ float g_feat[BN_TOT * KD];   // [B*N, 2C] interleaved (xs, agg)
__device__ int   g_is64;                // 1 if edge buffer is int64 viewed as int32 pairs

// ============================================================
// K0: detect edge dtype. Valid indices are < 2048, so if the
// buffer is int64, every odd int32 word is 0 (little-endian).
// ============================================================
__global__ void k_detect(const int* __restrict__ e) {
    const int t = threadIdx.x;
    int bad = 0;
    #pragma unroll
    for (int i = t; i < 256; i += 32) bad |= e[2 * i + 1];
    #pragma unroll
    for (int o = 16; o; o >>= 1) bad |= __shfl_xor_sync(0xffffffffu, bad, o);
    if (!t) g_is64 = (bad == 0) ? 1 : 0;
}

// ============================================================
// K1: transpose xs [B,C,N] -> xsT [B*N, C]
// ============================================================
__global__ void k_transpose(const float* __restrict__ x) {
    __shared__ float tile[32][33];
    const int b  = blockIdx.z;
    const int n0 = blockIdx.x * 32;
    const int c0 = blockIdx.y * 32;
    const float* xb = x + (size_t)b * Cc * Nn;
    #pragma unroll
    for (int i = 0; i < 32; i += 8)
        tile[threadIdx.y + i][threadIdx.x] =
            xb[(size_t)(c0 + threadIdx.y + i) * Nn + n0 + threadIdx.x];
    __syncthreads();
    float* xt = g_xsT + (size_t)b * Nn * Cc;
    #pragma unroll
    for (int i = 0; i < 32; i += 8)
        xt[(size_t)(n0 + threadIdx.y + i) * Cc + c0 + threadIdx.x] =
            tile[threadIdx.x][threadIdx.y + i];
}

// ============================================================
// K2: per-node attention pre-scores s_i, s_j (one warp per node)
// ============================================================
__global__ void k_scores(const float* __restrict__ aw) {
    const int gw   = (blockIdx.x * blockDim.x + threadIdx.x) >> 5;
    const int lane = threadIdx.x & 31;
    if (gw >= BN_TOT) return;
    const float4* v  = (const float4*)(g_xsT + (size_t)gw * Cc);
    const float4* wi = (const float4*)aw;
    const float4* wj = (const float4*)(aw + Cc);
    float ai = 0.f, aj = 0.f;
    #pragma unroll
    for (int r = 0; r < 2; r++) {
        const int idx = lane + r * 32;
        float4 xv = v[idx], w1 = wi[idx], w2 = wj[idx];
        ai += xv.x * w1.x + xv.y * w1.y + xv.z * w1.z + xv.w * w1.w;
        aj += xv.x * w2.x + xv.y * w2.y + xv.z * w2.z + xv.w * w2.w;
    }
    #pragma unroll
    for (int o = 16; o; o >>= 1) {
        ai += __shfl_xor_sync(0xffffffffu, ai, o);
        aj += __shfl_xor_sync(0xffffffffu, aj, o);
    }
    if (!lane) { g_si[gw] = ai; g_sj[gw] = aj; }
}

// ============================================================
// K3: per-node softmax over K neighbors (scalar gathers only)
// Handles both int32 and int64 edge buffers via g_is64 stride.
// All indices masked to [0, Nn) for fault-safety.
// ============================================================
__global__ void k_softmax(const int* __restrict__ edge,
                          const float* __restrict__ ab) {
    const int bn = blockIdx.x * blockDim.x + threadIdx.x;
    if (bn >= BN_TOT) return;
    const int sh = g_is64;               // 0: int32, 1: int64-as-pairs
    const int b  = bn >> 11;             // / 2048
    const int* e0 = edge + ((size_t)bn * Kk << sh);
    const int* e1 = edge + (((size_t)BN_TOT * Kk) << sh) + ((size_t)bn * Kk << sh);
    float ev[Kk]; int jv[Kk];
    const float abv = ab[0];
    float m = -1e30f;
    #pragma unroll
    for (int k = 0; k < Kk; k++) {
        const int i0 = e0[k << sh] & (Nn - 1);
        const int i1 = e1[k << sh] & (Nn - 1);
        jv[k] = i0;
        const float e = g_si[b * Nn + i1] + g_sj[b * Nn + i0] + abv;
        ev[k] = e;
        m = fmaxf(m, e);
    }
    float s = 0.f;
    #pragma unroll
    for (int k = 0; k < Kk; k++) { ev[k] = expf(ev[k] - m); s += ev[k]; }
    const float inv = 1.f / s;
    #pragma unroll
    for (int k = 0; k < Kk; k++) {
        g_w[bn * Kk + k] = ev[k] * inv;
        g_j[bn * Kk + k] = jv[k];
    }
}

// ============================================================
// K4: neighbor aggregation + interleaved feature build
//     feat[bn, 2c] = xs[bn,c], feat[bn, 2c+1] = agg[bn,c]
//     64 threads per node (float4 over C), 4 nodes per block
// ============================================================
__global__ __launch_bounds__(256) void k_agg() {
    const int node = threadIdx.x >> 6;
    const int t    = threadIdx.x & 63;
    const int bn   = blockIdx.x * 4 + node;
    const int b    = bn >> 11;
    const float* base = g_xsT + (size_t)b * Nn * Cc;
    const int c = t * 4;
    const float4 xc = *(const float4*)(g_xsT + (size_t)bn * Cc + c);
    float ax = 0.f, ay = 0.f, az = 0.f, aw_ = 0.f;
    const float* wp = g_w + bn * Kk;
    const int*   jp = g_j + bn * Kk;
    #pragma unroll
    for (int k = 0; k < Kk; k++) {
        const float wk = wp[k];
        const float4 g = *(const float4*)(base + (size_t)(jp[k] & (Nn - 1)) * Cc + c);
        ax += wk * g.x; ay += wk * g.y; az += wk * g.z; aw_ += wk * g.w;
    }
    float* f = g_feat + (size_t)bn * KD + 2 * c;
    ((float4*)f)[0] = make_float4(xc.x, ax, xc.y, ay);
    ((float4*)f)[1] = make_float4(xc.z, az, xc.w, aw_);
}

// ============================================================
// K5: conventional NT-SGEMM
//     out[b,o,n] = relu( nn_w[o,:] . feat[bn,:] + bias[o] )
//     128x128 tile, BK=8, double-buffered smem, 8x8 microtile
// ============================================================
__global__ __launch_bounds__(256)
void k_gemm(const float* __restrict__ A,      // nn_w [256, 512]
            const float* __restrict__ bias,   // nn_b [256]
            float* __restrict__ out) {        // [B, OUT, N]
    __shared__ __align__(16) float As[2][8][128];   // As[kk][m]
    __shared__ __align__(16) float Bs[2][8][128];   // Bs[kk][n]

    const int tid  = threadIdx.x;
    const int m0   = blockIdx.y * 128;
    const int n0   = blockIdx.x * 128;
    const int lrow = tid >> 1;          // 0..127
    const int lcol = (tid & 1) * 4;     // 0 or 4

    const float* Ap = A      + (size_t)(m0 + lrow) * KD + lcol;
    const float* Bp = g_feat + (size_t)(n0 + lrow) * KD + lcol;

    float acc[8][8];
    #pragma unroll
    for (int i = 0; i < 8; i++)
        #pragma unroll
        for (int j = 0; j < 8; j++) acc[i][j] = 0.f;

    {
        const float4 av = *(const float4*)Ap;
        const float4 bv = *(const float4*)Bp;
        As[0][lcol + 0][lrow] = av.x;
        As[0][lcol + 1][lrow] = av.y;
        As[0][lcol + 2][lrow] = av.z;
        As[0][lcol + 3][lrow] = av.w;
        Bs[0][lcol + 0][lrow] = bv.x;
        Bs[0][lcol + 1][lrow] = bv.y;
        Bs[0][lcol + 2][lrow] = bv.z;
        Bs[0][lcol + 3][lrow] = bv.w;
    }
    __syncthreads();

    const int tx = tid & 15;   // column group (n)
    const int ty = tid >> 4;   // row group (m)

    #pragma unroll 1
    for (int kt = 0; kt < KD / 8; kt++) {
        const int buf = kt & 1;
        float4 av2, bv2;
        if (kt < KD / 8 - 1) {
            av2 = *(const float4*)(Ap + (kt + 1) * 8);
            bv2 = *(const float4*)(Bp + (kt + 1) * 8);
        }
        #pragma unroll
        for (int kk = 0; kk < 8; kk++) {
            const float4 a0 = *(const float4*)&As[buf][kk][4 * ty];
            const float4 a1 = *(const float4*)&As[buf][kk][64 + 4 * ty];
            const float4 b0 = *(const float4*)&Bs[buf][kk][4 * tx];
            const float4 b1 = *(const float4*)&Bs[buf][kk][64 + 4 * tx];
            const float am[8] = {a0.x, a0.y, a0.z, a0.w, a1.x, a1.y, a1.z, a1.w};
            const float bn_[8] = {b0.x, b0.y, b0.z, b0.w, b1.x, b1.y, b1.z, b1.w};
            #pragma unroll
            for (int i = 0; i < 8; i++)
                #pragma unroll
                for (int j = 0; j < 8; j++)
                    acc[i][j] = fmaf(am[i], bn_[j], acc[i][j]);
        }
        if (kt < KD / 8 - 1) {
            const int nbuf = buf ^ 1;
            As[nbuf][lcol + 0][lrow] = av2.x;
            As[nbuf][lcol + 1][lrow] = av2.y;
            As[nbuf][lcol + 2][lrow] = av2.z;
            As[nbuf][lcol + 3][lrow] = av2.w;
            Bs[nbuf][lcol + 0][lrow] = bv2.x;
            Bs[nbuf][lcol + 1][lrow] = bv2.y;
            Bs[nbuf][lcol + 2][lrow] = bv2.z;
            Bs[nbuf][lcol + 3][lrow] = bv2.w;
            __syncthreads();
        }
    }

    const int bidx = n0 >> 11;             // batch of this 128-col tile
    float* obase = out + (size_t)bidx * OUTd * Nn + (n0 & 2047);
    #pragma unroll
    for (int i = 0; i < 8; i++) {
        const int rloc = (i < 4) ? (4 * ty + i) : (64 + 4 * ty + (i - 4));
        const int row  = m0 + rloc;
        const float bv = bias[row];
        float4 o0, o1;
        o0.x = fmaxf(acc[i][0] + bv, 0.f);
        o0.y = fmaxf(acc[i][1] + bv, 0.f);
        o0.z = fmaxf(acc[i][2] + bv, 0.f);
        o0.w = fmaxf(acc[i][3] + bv, 0.f);
        o1.x = fmaxf(acc[i][4] + bv, 0.f);
        o1.y = fmaxf(acc[i][5] + bv, 0.f);
        o1.z = fmaxf(acc[i][6] + bv, 0.f);
        o1.w = fmaxf(acc[i][7] + bv, 0.f);
        *(float4*)(obase + (size_t)row * Nn + 4 * tx)      = o0;
        *(float4*)(obase + (size_t)row * Nn + 64 + 4 * tx) = o1;
    }
}

// ============================================================
// launch
// ============================================================
extern "C" void kernel_launch(void* const* d_in, const int* in_sizes, int n_in,
                              void* d_out, int out_size) {
    const float* x    = (const float*)d_in[0];
    const int*   edge = (const int*)d_in[1];
    const float* a_w  = (const float*)d_in[2];
    const float* a_b  = (const float*)d_in[3];
    const float* nn_w = (const float*)d_in[4];
    const float* nn_b = (const float*)d_in[5];
    float*       out  = (float*)d_out;

    k_detect  <<<1, 32>>>(edge);
    k_transpose<<<dim3(Nn / 32, Cc / 32, Bb), dim3(32, 8)>>>(x);
    k_scores  <<<(BN_TOT * 32) / 256, 256>>>(a_w);
    k_softmax <<<BN_TOT / 256, 256>>>(edge, a_b);
    k_agg     <<<BN_TOT / 4, 256>>>();
    k_gemm    <<<dim3(BN_TOT / 128, OUTd / 128), 256>>>(nn_w, nn_b, out);
}